// round 3
// baseline (speedup 1.0000x reference)
#include <cuda_runtime.h>
#include <cuda_bf16.h>
#include <cstdint>
#include <math.h>

// ============================================================================
// Problem constants
// ============================================================================
#define NB   32      // batch
#define SEQ  4096    // sequence length
#define DIM  256     // DEC_DIM == ENC_DIM == ATT_UNITS
#define BM   64      // s-rows per CTA
#define BK   32      // k-chunk
#define NTILES_S (SEQ / BM)             // 64
#define CTX_CHUNKS 8
#define CTX_S (SEQ / CTX_CHUNKS)        // 512

// ============================================================================
// Device scratch (no allocations allowed)
// ============================================================================
__device__ float g_q[NB * DIM];              // q = dh@w1 + b1  (fp32 exact)
__device__ float g_score[NB * SEQ];          // raw scores
__device__ float g_partial[NB * CTX_CHUNKS * DIM];

// ============================================================================
// Portable PTX helpers (base sm_80+ ISA only: cp.async + mma.sync)
// ============================================================================
static __device__ __forceinline__ uint32_t smem_u32(const void* p) {
    uint32_t a;
    asm("{ .reg .u64 t; cvta.to.shared.u64 t, %1; cvt.u32.u64 %0, t; }"
        : "=r"(a) : "l"(p));
    return a;
}

static __device__ __forceinline__ uint32_t f2tf32(float x) {
    uint32_t r;
    asm("cvt.rna.tf32.f32 %0, %1;" : "=r"(r) : "f"(x));
    return r;
}

#define CP_ASYNC16(dst_u32, src_ptr) \
    asm volatile("cp.async.cg.shared.global [%0], [%1], 16;" \
                 :: "r"(dst_u32), "l"(src_ptr))
#define CP_COMMIT() asm volatile("cp.async.commit_group;" ::: "memory")
#define CP_WAIT(N)  asm volatile("cp.async.wait_group %0;" :: "n"(N) : "memory")

// mma.sync m16n8k8 tf32: D = A*B + D (fp32 accum)
static __device__ __forceinline__ void mma_tf32(
    float& d0, float& d1, float& d2, float& d3,
    uint32_t a0, uint32_t a1, uint32_t a2, uint32_t a3,
    uint32_t b0, uint32_t b1)
{
    asm volatile(
        "mma.sync.aligned.m16n8k8.row.col.f32.tf32.tf32.f32 "
        "{%0,%1,%2,%3}, {%4,%5,%6,%7}, {%8,%9}, {%0,%1,%2,%3};"
        : "+f"(d0), "+f"(d1), "+f"(d2), "+f"(d3)
        : "r"(a0), "r"(a1), "r"(a2), "r"(a3), "r"(b0), "r"(b1));
}

// ============================================================================
// Dynamic SMEM layout for score kernel (bytes)
//   A tile: [64 rows][36 words] per stage (stride 36 -> bank = 4g+c, conflict-free)
//   B tile: [32 rows][264 words] per stage (264%32==8 -> bank = 8c+g, conflict-free)
// ============================================================================
static constexpr int SME_Q   = 0;                      // 256 f32: q+b2
static constexpr int SME_V   = 1024;                   // 256 f32: v
static constexpr int SME_RED = 2048;                   // 4*64 f32
static constexpr int A_STRIDE = 36;                    // words
static constexpr int B_STRIDE = 264;                   // words
static constexpr int SME_A0  = 3072;
static constexpr int A_STAGE = BM * A_STRIDE * 4;      // 9216
static constexpr int SME_A1  = SME_A0 + A_STAGE;       // 12288
static constexpr int SME_B0  = SME_A1 + A_STAGE;       // 21504
static constexpr int B_STAGE = BK * B_STRIDE * 4;      // 33792
static constexpr int SME_B1  = SME_B0 + B_STAGE;       // 55296
static constexpr int SMEM_TOTAL = SME_B1 + B_STAGE;    // 89088

// ============================================================================
// Kernel 1: q = dh @ w1 + b1   (fp32 exact, trivial cost)
// ============================================================================
__global__ void prep_q_kernel(const float* __restrict__ dh,
                              const float* __restrict__ w1,
                              const float* __restrict__ b1) {
    __shared__ float d[DIM];
    int b = blockIdx.x, a = threadIdx.x;
    d[a] = dh[b * DIM + a];
    __syncthreads();
    float acc = b1[a];
#pragma unroll 8
    for (int e = 0; e < DIM; ++e) acc = fmaf(d[e], w1[e * DIM + a], acc);
    g_q[b * DIM + a] = acc;
}

// ============================================================================
// Kernel 2: score[b][s] = v . tanh(q + b2 + enc@w2) + vbias
// tf32 mma.sync GEMM, BM=64 x BN=256 x K=256, fused tanh/dot epilogue.
// grid (NTILES_S, NB), 256 threads, 8 warps = 2(m) x 4(n), warp tile 32x64.
// ============================================================================
__global__ __launch_bounds__(256, 2)
void score_kernel(const float* __restrict__ enc,
                  const float* __restrict__ w2,
                  const float* __restrict__ vker,
                  const float* __restrict__ vbias,
                  const float* __restrict__ b2) {
    extern __shared__ char smem[];
    const uint32_t sbase = smem_u32(smem);
    float* qs  = (float*)(smem + SME_Q);
    float* vs  = (float*)(smem + SME_V);
    float* red = (float*)(smem + SME_RED);

    const int tid = threadIdx.x;
    const int wid = tid >> 5, lid = tid & 31;
    const int wm = wid >> 2;          // 0..1  (m group: rows wm*32..+32)
    const int wn = wid & 3;           // 0..3  (n group: cols wn*64..+64)
    const int g  = lid >> 2;          // 0..7
    const int c  = lid & 3;           // 0..3
    const int b  = blockIdx.y;
    const int s0 = blockIdx.x * BM;

    // stage q+b2 and v
    qs[tid] = g_q[b * DIM + tid] + b2[tid];
    vs[tid] = vker[tid];
    const float vb0 = vbias[0];

    const float* encA = enc + ((size_t)b * SEQ + s0) * DIM;

    // ---- async loaders ----------------------------------------------------
    auto load_stage = [&](int stage, int kb) {
        const int k0 = kb * BK;
        // A: 64 rows x 32 floats = 512 x 16B chunks, 2 per thread
        uint32_t abase = sbase + (stage ? SME_A1 : SME_A0);
#pragma unroll
        for (int i = 0; i < 2; ++i) {
            int chunk = i * 256 + tid;
            int r = chunk >> 3, j = chunk & 7;        // j: 16B chunk in row
            uint32_t dst = abase + (uint32_t)(r * A_STRIDE + j * 4) * 4;
            CP_ASYNC16(dst, encA + (size_t)r * DIM + k0 + j * 4);
        }
        // B: 32 rows x 256 floats = 2048 x 16B chunks, 8 per thread
        uint32_t bbase = sbase + (stage ? SME_B1 : SME_B0);
#pragma unroll
        for (int i = 0; i < 8; ++i) {
            int chunk = i * 256 + tid;
            int k = chunk >> 6, j = chunk & 63;
            uint32_t dst = bbase + (uint32_t)(k * B_STRIDE + j * 4) * 4;
            CP_ASYNC16(dst, w2 + (size_t)(k0 + k) * DIM + j * 4);
        }
    };

    float acc[2][8][4];
#pragma unroll
    for (int mt = 0; mt < 2; ++mt)
#pragma unroll
        for (int nt = 0; nt < 8; ++nt)
#pragma unroll
            for (int j = 0; j < 4; ++j) acc[mt][nt][j] = 0.0f;

    load_stage(0, 0); CP_COMMIT();
    load_stage(1, 1); CP_COMMIT();

    const int NKB = DIM / BK;   // 8
    for (int kb = 0; kb < NKB; ++kb) {
        if (kb < NKB - 2) { CP_WAIT(1); } else { CP_WAIT(0); }
        __syncthreads();

        const float* As = (const float*)(smem + ((kb & 1) ? SME_A1 : SME_A0));
        const float* Bs = (const float*)(smem + ((kb & 1) ? SME_B1 : SME_B0));

#pragma unroll
        for (int ks = 0; ks < 4; ++ks) {
            const int kk = ks * 8;
            // A fragments: rows wm*32 + mt*16 + {g, g+8}, cols kk + {c, c+4}
            uint32_t af[2][4];
#pragma unroll
            for (int mt = 0; mt < 2; ++mt) {
                int r0 = (wm * 32 + mt * 16 + g) * A_STRIDE;
                af[mt][0] = f2tf32(As[r0 + kk + c]);
                af[mt][1] = f2tf32(As[r0 + 8 * A_STRIDE + kk + c]);
                af[mt][2] = f2tf32(As[r0 + kk + c + 4]);
                af[mt][3] = f2tf32(As[r0 + 8 * A_STRIDE + kk + c + 4]);
            }
            // B fragments: rows kk + {c, c+4}, col wn*64 + nt*8 + g
            uint32_t bf[8][2];
#pragma unroll
            for (int nt = 0; nt < 8; ++nt) {
                int col = wn * 64 + nt * 8 + g;
                bf[nt][0] = f2tf32(Bs[(kk + c) * B_STRIDE + col]);
                bf[nt][1] = f2tf32(Bs[(kk + c + 4) * B_STRIDE + col]);
            }
#pragma unroll
            for (int mt = 0; mt < 2; ++mt)
#pragma unroll
                for (int nt = 0; nt < 8; ++nt)
                    mma_tf32(acc[mt][nt][0], acc[mt][nt][1],
                             acc[mt][nt][2], acc[mt][nt][3],
                             af[mt][0], af[mt][1], af[mt][2], af[mt][3],
                             bf[nt][0], bf[nt][1]);
        }
        __syncthreads();
        if (kb + 2 < NKB) { load_stage(kb & 1, kb + 2); CP_COMMIT(); }
    }

    // ---- epilogue: tanh(q + k) . v, reduce over N ------------------------
    // Thread holds rows {wm*32+mt*16+g, +8}, cols {wn*64+nt*8+2c, +1}
#pragma unroll
    for (int mt = 0; mt < 2; ++mt) {
#pragma unroll
        for (int h = 0; h < 2; ++h) {
            float p = 0.0f;
#pragma unroll
            for (int nt = 0; nt < 8; ++nt) {
#pragma unroll
                for (int j = 0; j < 2; ++j) {
                    int col = wn * 64 + nt * 8 + 2 * c + j;
                    float kv = acc[mt][nt][h * 2 + j];
                    p = fmaf(tanhf(qs[col] + kv), vs[col], p);
                }
            }
            // reduce over the 4 c-lanes (adjacent lanes)
            p += __shfl_xor_sync(0xFFFFFFFF, p, 1);
            p += __shfl_xor_sync(0xFFFFFFFF, p, 2);
            if (c == 0) {
                int row = wm * 32 + mt * 16 + g + h * 8;   // 0..63
                red[wn * 64 + row] = p;
            }
        }
    }
    __syncthreads();
    if (tid < BM) {
        float s = vb0 + red[tid] + red[64 + tid] + red[128 + tid] + red[192 + tid];
        g_score[b * SEQ + s0 + tid] = s;
    }
}

// ============================================================================
// Kernel 3: softmax over S per batch, writes attention weights to d_out
// ============================================================================
__global__ void softmax_kernel(float* __restrict__ out) {
    __shared__ float red[256];
    const int b = blockIdx.x, tid = threadIdx.x;
    const float* s = g_score + b * SEQ;

    float v[16];
    float m = -1e30f;
#pragma unroll
    for (int j = 0; j < 16; ++j) {
        v[j] = s[tid + j * 256];
        m = fmaxf(m, v[j]);
    }
    red[tid] = m; __syncthreads();
    for (int st = 128; st > 0; st >>= 1) {
        if (tid < st) red[tid] = fmaxf(red[tid], red[tid + st]);
        __syncthreads();
    }
    m = red[0]; __syncthreads();

    float sum = 0.0f;
#pragma unroll
    for (int j = 0; j < 16; ++j) { v[j] = expf(v[j] - m); sum += v[j]; }
    red[tid] = sum; __syncthreads();
    for (int st = 128; st > 0; st >>= 1) {
        if (tid < st) red[tid] += red[tid + st];
        __syncthreads();
    }
    const float inv = 1.0f / red[0];

    float* wout = out + NB * DIM + b * SEQ;   // weights after context region
#pragma unroll
    for (int j = 0; j < 16; ++j) wout[tid + j * 256] = v[j] * inv;
}

// ============================================================================
// Kernel 4: partial context sums (deterministic split over S)
// ============================================================================
__global__ void ctx_partial_kernel(const float* __restrict__ enc,
                                   const float* __restrict__ out) {
    __shared__ float ws[CTX_S];
    const int b = blockIdx.y, ch = blockIdx.x, tid = threadIdx.x;
    const float* wrow = out + NB * DIM + b * SEQ + ch * CTX_S;
    for (int i = tid; i < CTX_S; i += 256) ws[i] = wrow[i];
    __syncthreads();

    const float* e = enc + ((size_t)b * SEQ + ch * CTX_S) * DIM + tid;
    float a0 = 0.f, a1 = 0.f, a2 = 0.f, a3 = 0.f;
#pragma unroll 4
    for (int s = 0; s < CTX_S; s += 4) {
        a0 = fmaf(ws[s + 0], e[(size_t)(s + 0) * DIM], a0);
        a1 = fmaf(ws[s + 1], e[(size_t)(s + 1) * DIM], a1);
        a2 = fmaf(ws[s + 2], e[(size_t)(s + 2) * DIM], a2);
        a3 = fmaf(ws[s + 3], e[(size_t)(s + 3) * DIM], a3);
    }
    g_partial[(b * CTX_CHUNKS + ch) * DIM + tid] = (a0 + a1) + (a2 + a3);
}

// ============================================================================
// Kernel 5: final context reduction
// ============================================================================
__global__ void ctx_final_kernel(float* __restrict__ out) {
    const int b = blockIdx.x, a = threadIdx.x;
    float acc = 0.0f;
#pragma unroll
    for (int c = 0; c < CTX_CHUNKS; ++c)
        acc += g_partial[(b * CTX_CHUNKS + c) * DIM + a];
    out[b * DIM + a] = acc;
}

// ============================================================================
// kernel_launch
// ============================================================================
extern "C" void kernel_launch(void* const* d_in, const int* in_sizes, int n_in,
                              void* d_out, int out_size) {
    const float* dh  = (const float*)d_in[0];
    const float* enc = (const float*)d_in[1];
    const float* w1  = (const float*)d_in[2];
    const float* b1  = (const float*)d_in[3];
    const float* w2  = (const float*)d_in[4];
    const float* b2  = (const float*)d_in[5];
    const float* vk  = (const float*)d_in[6];
    const float* vb  = (const float*)d_in[7];
    float* out = (float*)d_out;

    cudaFuncSetAttribute(score_kernel,
                         cudaFuncAttributeMaxDynamicSharedMemorySize, SMEM_TOTAL);

    prep_q_kernel<<<NB, DIM>>>(dh, w1, b1);
    score_kernel<<<dim3(NTILES_S, NB), 256, SMEM_TOTAL>>>(enc, w2, vk, vb, b2);
    softmax_kernel<<<NB, 256>>>(out);
    ctx_partial_kernel<<<dim3(CTX_CHUNKS, NB), 256>>>(enc, out);
    ctx_final_kernel<<<NB, DIM>>>(out);
}

// round 5
// speedup vs baseline: 1.1500x; 1.1500x over previous
#include <cuda_runtime.h>
#include <cstdint>
#include <math.h>

// ============================================================================
// Problem constants
// ============================================================================
#define NB   32      // batch
#define SEQ  4096    // sequence length
#define DIM  256     // DEC_DIM == ENC_DIM == ATT_UNITS
#define BM   64      // s-rows per CTA
#define BK   32      // k-chunk
#define NTILES_S (SEQ / BM)             // 64
#define CTX_CHUNKS 32
#define CTX_S (SEQ / CTX_CHUNKS)        // 128

// ============================================================================
// Device scratch (no allocations allowed)
// ============================================================================
__device__ float g_q[NB * DIM];              // q = dh@w1 + b1  (fp32 exact)
__device__ float g_w2r[DIM * DIM];           // w2 rounded to tf32 (rna)
__device__ float g_score[NB * SEQ];          // raw scores
__device__ float g_partial[NB * CTX_CHUNKS * DIM];

// ============================================================================
// Portable PTX helpers (base sm_80+ ISA only: cp.async + mma.sync)
// ============================================================================
static __device__ __forceinline__ uint32_t smem_u32(const void* p) {
    uint32_t a;
    asm("{ .reg .u64 t; cvta.to.shared.u64 t, %1; cvt.u32.u64 %0, t; }"
        : "=r"(a) : "l"(p));
    return a;
}

// cvt.rna.tf32.f32 requires a .b32 destination register
static __device__ __forceinline__ uint32_t f2tf32_rna(float x) {
    uint32_t r;
    asm("cvt.rna.tf32.f32 %0, %1;" : "=r"(r) : "f"(x));
    return r;
}

#define CP_ASYNC16(dst_u32, src_ptr) \
    asm volatile("cp.async.cg.shared.global [%0], [%1], 16;" \
                 :: "r"(dst_u32), "l"(src_ptr))
#define CP_COMMIT() asm volatile("cp.async.commit_group;" ::: "memory")
#define CP_WAIT(N)  asm volatile("cp.async.wait_group %0;" :: "n"(N) : "memory")

// mma.sync m16n8k8 tf32: D = A*B + D (fp32 accum). Operand registers carry raw
// float bits; the tensor core reads only the tf32 bits (truncation semantics).
static __device__ __forceinline__ void mma_tf32(
    float& d0, float& d1, float& d2, float& d3,
    uint32_t a0, uint32_t a1, uint32_t a2, uint32_t a3,
    uint32_t b0, uint32_t b1)
{
    asm volatile(
        "mma.sync.aligned.m16n8k8.row.col.f32.tf32.tf32.f32 "
        "{%0,%1,%2,%3}, {%4,%5,%6,%7}, {%8,%9}, {%0,%1,%2,%3};"
        : "+f"(d0), "+f"(d1), "+f"(d2), "+f"(d3)
        : "r"(a0), "r"(a1), "r"(a2), "r"(a3), "r"(b0), "r"(b1));
}

// ============================================================================
// Dynamic SMEM layout for score kernel (bytes)
//   A tile: [64 rows][36 words] per stage (stride 36 -> bank = 4g+c, conflict-free)
//   B tile: [32 rows][264 words] per stage (264%32==8 -> bank = 8c+g, conflict-free)
// ============================================================================
static constexpr int SME_Q   = 0;                      // 256 f32: q+b2
static constexpr int SME_V   = 1024;                   // 256 f32: v
static constexpr int SME_RED = 2048;                   // 4*64 f32
static constexpr int A_STRIDE = 36;                    // words
static constexpr int B_STRIDE = 264;                   // words
static constexpr int SME_A0  = 3072;
static constexpr int A_STAGE = BM * A_STRIDE * 4;      // 9216
static constexpr int SME_A1  = SME_A0 + A_STAGE;       // 12288
static constexpr int SME_B0  = SME_A1 + A_STAGE;       // 21504
static constexpr int B_STAGE = BK * B_STRIDE * 4;      // 33792
static constexpr int SME_B1  = SME_B0 + B_STAGE;       // 55296
static constexpr int SMEM_TOTAL = SME_B1 + B_STAGE;    // 89088

// ============================================================================
// Kernel 1: q = dh @ w1 + b1   (fp32 exact, trivial cost)
// ============================================================================
__global__ void prep_q_kernel(const float* __restrict__ dh,
                              const float* __restrict__ w1,
                              const float* __restrict__ b1) {
    __shared__ float d[DIM];
    int b = blockIdx.x, a = threadIdx.x;
    d[a] = dh[b * DIM + a];
    __syncthreads();
    float acc = b1[a];
#pragma unroll 8
    for (int e = 0; e < DIM; ++e) acc = fmaf(d[e], w1[e * DIM + a], acc);
    g_q[b * DIM + a] = acc;
}

// ============================================================================
// Kernel 1b: pre-round w2 to tf32 (rna) once — removes all B-side cvts from
// the score mainloop.
// ============================================================================
__global__ void prep_w2_kernel(const float* __restrict__ w2) {
    int i = (blockIdx.x * 256 + threadIdx.x) * 4;
    float4 v = *(const float4*)(w2 + i);
    float4 o;
    o.x = __uint_as_float(f2tf32_rna(v.x));
    o.y = __uint_as_float(f2tf32_rna(v.y));
    o.z = __uint_as_float(f2tf32_rna(v.z));
    o.w = __uint_as_float(f2tf32_rna(v.w));
    *(float4*)(g_w2r + i) = o;
}

// ============================================================================
// Kernel 2: score[b][s] = v . tanh(q + b2 + enc@w2) + vbias
// tf32 mma.sync GEMM, BM=64 x BN=256 x K=256, fused tanh/dot epilogue.
// grid (NTILES_S, NB), 256 threads, 8 warps = 2(m) x 4(n), warp tile 32x64.
// A is truncated to tf32 (HW ignores low bits); B pre-rounded in g_w2r.
// ============================================================================
__global__ __launch_bounds__(256, 2)
void score_kernel(const float* __restrict__ enc,
                  const float* __restrict__ vker,
                  const float* __restrict__ vbias,
                  const float* __restrict__ b2) {
    extern __shared__ char smem[];
    const uint32_t sbase = smem_u32(smem);
    float* qs  = (float*)(smem + SME_Q);
    float* vs  = (float*)(smem + SME_V);
    float* red = (float*)(smem + SME_RED);

    const int tid = threadIdx.x;
    const int wid = tid >> 5, lid = tid & 31;
    const int wm = wid >> 2;          // 0..1  (m group: rows wm*32..+32)
    const int wn = wid & 3;           // 0..3  (n group: cols wn*64..+64)
    const int g  = lid >> 2;          // 0..7
    const int c  = lid & 3;           // 0..3
    const int b  = blockIdx.y;
    const int s0 = blockIdx.x * BM;

    // stage q+b2 and v
    qs[tid] = g_q[b * DIM + tid] + b2[tid];
    vs[tid] = vker[tid];
    const float vb0 = vbias[0];

    const float* encA = enc + ((size_t)b * SEQ + s0) * DIM;

    // ---- async loaders ----------------------------------------------------
    auto load_stage = [&](int stage, int kb) {
        const int k0 = kb * BK;
        // A: 64 rows x 32 floats = 512 x 16B chunks, 2 per thread
        uint32_t abase = sbase + (stage ? SME_A1 : SME_A0);
#pragma unroll
        for (int i = 0; i < 2; ++i) {
            int chunk = i * 256 + tid;
            int r = chunk >> 3, j = chunk & 7;        // j: 16B chunk in row
            uint32_t dst = abase + (uint32_t)(r * A_STRIDE + j * 4) * 4;
            CP_ASYNC16(dst, encA + (size_t)r * DIM + k0 + j * 4);
        }
        // B: 32 rows x 256 floats = 2048 x 16B chunks, 8 per thread
        uint32_t bbase = sbase + (stage ? SME_B1 : SME_B0);
#pragma unroll
        for (int i = 0; i < 8; ++i) {
            int chunk = i * 256 + tid;
            int k = chunk >> 6, j = chunk & 63;
            uint32_t dst = bbase + (uint32_t)(k * B_STRIDE + j * 4) * 4;
            CP_ASYNC16(dst, g_w2r + (size_t)(k0 + k) * DIM + j * 4);
        }
    };

    float acc[2][8][4];
#pragma unroll
    for (int mt = 0; mt < 2; ++mt)
#pragma unroll
        for (int nt = 0; nt < 8; ++nt)
#pragma unroll
            for (int j = 0; j < 4; ++j) acc[mt][nt][j] = 0.0f;

    load_stage(0, 0); CP_COMMIT();
    load_stage(1, 1); CP_COMMIT();

    const int NKB = DIM / BK;   // 8
    for (int kb = 0; kb < NKB; ++kb) {
        if (kb < NKB - 2) { CP_WAIT(1); } else { CP_WAIT(0); }
        __syncthreads();

        const float* As = (const float*)(smem + ((kb & 1) ? SME_A1 : SME_A0));
        const float* Bs = (const float*)(smem + ((kb & 1) ? SME_B1 : SME_B0));

#pragma unroll
        for (int ks = 0; ks < 4; ++ks) {
            const int kk = ks * 8;
            // A fragments: rows wm*32 + mt*16 + {g, g+8}, cols kk + {c, c+4}
            uint32_t af[2][4];
#pragma unroll
            for (int mt = 0; mt < 2; ++mt) {
                int r0 = (wm * 32 + mt * 16 + g) * A_STRIDE;
                af[mt][0] = __float_as_uint(As[r0 + kk + c]);
                af[mt][1] = __float_as_uint(As[r0 + 8 * A_STRIDE + kk + c]);
                af[mt][2] = __float_as_uint(As[r0 + kk + c + 4]);
                af[mt][3] = __float_as_uint(As[r0 + 8 * A_STRIDE + kk + c + 4]);
            }
            // B fragments: rows kk + {c, c+4}, col wn*64 + nt*8 + g
            uint32_t bf[8][2];
#pragma unroll
            for (int nt = 0; nt < 8; ++nt) {
                int col = wn * 64 + nt * 8 + g;
                bf[nt][0] = __float_as_uint(Bs[(kk + c) * B_STRIDE + col]);
                bf[nt][1] = __float_as_uint(Bs[(kk + c + 4) * B_STRIDE + col]);
            }
#pragma unroll
            for (int mt = 0; mt < 2; ++mt)
#pragma unroll
                for (int nt = 0; nt < 8; ++nt)
                    mma_tf32(acc[mt][nt][0], acc[mt][nt][1],
                             acc[mt][nt][2], acc[mt][nt][3],
                             af[mt][0], af[mt][1], af[mt][2], af[mt][3],
                             bf[nt][0], bf[nt][1]);
        }
        __syncthreads();
        if (kb + 2 < NKB) { load_stage(kb & 1, kb + 2); CP_COMMIT(); }
    }

    // ---- epilogue: tanh(q + k) . v, reduce over N ------------------------
    // Thread holds rows {wm*32+mt*16+g, +8}, cols {wn*64+nt*8+2c, +1}
#pragma unroll
    for (int mt = 0; mt < 2; ++mt) {
#pragma unroll
        for (int h = 0; h < 2; ++h) {
            float p = 0.0f;
#pragma unroll
            for (int nt = 0; nt < 8; ++nt) {
#pragma unroll
                for (int j = 0; j < 2; ++j) {
                    int col = wn * 64 + nt * 8 + 2 * c + j;
                    float kv = acc[mt][nt][h * 2 + j];
                    p = fmaf(tanhf(qs[col] + kv), vs[col], p);
                }
            }
            // reduce over the 4 c-lanes (adjacent lanes)
            p += __shfl_xor_sync(0xFFFFFFFF, p, 1);
            p += __shfl_xor_sync(0xFFFFFFFF, p, 2);
            if (c == 0) {
                int row = wm * 32 + mt * 16 + g + h * 8;   // 0..63
                red[wn * 64 + row] = p;
            }
        }
    }
    __syncthreads();
    if (tid < BM) {
        float s = vb0 + red[tid] + red[64 + tid] + red[128 + tid] + red[192 + tid];
        g_score[b * SEQ + s0 + tid] = s;
    }
}

// ============================================================================
// Kernel 3: softmax over S per batch, writes attention weights to d_out
// ============================================================================
__global__ void softmax_kernel(float* __restrict__ out) {
    __shared__ float red[256];
    const int b = blockIdx.x, tid = threadIdx.x;
    const float* s = g_score + b * SEQ;

    float v[16];
    float m = -1e30f;
#pragma unroll
    for (int j = 0; j < 16; ++j) {
        v[j] = s[tid + j * 256];
        m = fmaxf(m, v[j]);
    }
    red[tid] = m; __syncthreads();
    for (int st = 128; st > 0; st >>= 1) {
        if (tid < st) red[tid] = fmaxf(red[tid], red[tid + st]);
        __syncthreads();
    }
    m = red[0]; __syncthreads();

    float sum = 0.0f;
#pragma unroll
    for (int j = 0; j < 16; ++j) { v[j] = expf(v[j] - m); sum += v[j]; }
    red[tid] = sum; __syncthreads();
    for (int st = 128; st > 0; st >>= 1) {
        if (tid < st) red[tid] += red[tid + st];
        __syncthreads();
    }
    const float inv = 1.0f / red[0];

    float* wout = out + NB * DIM + b * SEQ;   // weights after context region
#pragma unroll
    for (int j = 0; j < 16; ++j) wout[tid + j * 256] = v[j] * inv;
}

// ============================================================================
// Kernel 4: partial context sums (deterministic split over S)
// grid (CTX_CHUNKS, NB) = (32, 32) -> 1024 CTAs for occupancy/MLP
// ============================================================================
__global__ void ctx_partial_kernel(const float* __restrict__ enc,
                                   const float* __restrict__ out) {
    __shared__ float ws[CTX_S];
    const int b = blockIdx.y, ch = blockIdx.x, tid = threadIdx.x;
    const float* wrow = out + NB * DIM + b * SEQ + ch * CTX_S;
    if (tid < CTX_S) ws[tid] = wrow[tid];
    __syncthreads();

    const float* e = enc + ((size_t)b * SEQ + ch * CTX_S) * DIM + tid;
    float a0 = 0.f, a1 = 0.f, a2 = 0.f, a3 = 0.f;
#pragma unroll 8
    for (int s = 0; s < CTX_S; s += 4) {
        a0 = fmaf(ws[s + 0], e[(size_t)(s + 0) * DIM], a0);
        a1 = fmaf(ws[s + 1], e[(size_t)(s + 1) * DIM], a1);
        a2 = fmaf(ws[s + 2], e[(size_t)(s + 2) * DIM], a2);
        a3 = fmaf(ws[s + 3], e[(size_t)(s + 3) * DIM], a3);
    }
    g_partial[(b * CTX_CHUNKS + ch) * DIM + tid] = (a0 + a1) + (a2 + a3);
}

// ============================================================================
// Kernel 5: final context reduction
// ============================================================================
__global__ void ctx_final_kernel(float* __restrict__ out) {
    const int b = blockIdx.x, a = threadIdx.x;
    float acc = 0.0f;
#pragma unroll
    for (int c = 0; c < CTX_CHUNKS; ++c)
        acc += g_partial[(b * CTX_CHUNKS + c) * DIM + a];
    out[b * DIM + a] = acc;
}

// ============================================================================
// kernel_launch
// ============================================================================
extern "C" void kernel_launch(void* const* d_in, const int* in_sizes, int n_in,
                              void* d_out, int out_size) {
    const float* dh  = (const float*)d_in[0];
    const float* enc = (const float*)d_in[1];
    const float* w1  = (const float*)d_in[2];
    const float* b1  = (const float*)d_in[3];
    const float* w2  = (const float*)d_in[4];
    const float* b2  = (const float*)d_in[5];
    const float* vk  = (const float*)d_in[6];
    const float* vb  = (const float*)d_in[7];
    float* out = (float*)d_out;

    cudaFuncSetAttribute(score_kernel,
                         cudaFuncAttributeMaxDynamicSharedMemorySize, SMEM_TOTAL);

    prep_q_kernel<<<NB, DIM>>>(dh, w1, b1);
    prep_w2_kernel<<<DIM * DIM / 1024, 256>>>(w2);
    score_kernel<<<dim3(NTILES_S, NB), 256, SMEM_TOTAL>>>(enc, vk, vb, b2);
    softmax_kernel<<<NB, 256>>>(out);
    ctx_partial_kernel<<<dim3(CTX_CHUNKS, NB), 256>>>(enc, out);
    ctx_final_kernel<<<NB, DIM>>>(out);
}

// round 6
// speedup vs baseline: 1.4226x; 1.2371x over previous
#include <cuda_runtime.h>
#include <cuda_fp16.h>
#include <cstdint>
#include <math.h>

// ============================================================================
// Problem constants
// ============================================================================
#define NB   32      // batch
#define SEQ  4096    // sequence length
#define DIM  256     // DEC_DIM == ENC_DIM == ATT_UNITS
#define BM   64      // s-rows per CTA
#define BK   32      // k per B pipeline stage
#define NTILES_S (SEQ / BM)             // 64
#define CTX_CHUNKS 32
#define CTX_S (SEQ / CTX_CHUNKS)        // 128

// ============================================================================
// Device scratch (no allocations allowed)
// ============================================================================
__device__ float  g_q[NB * DIM];             // q = dh@w1 + b1  (fp32 exact)
__device__ __half g_w2t_h[DIM * DIM];        // w2 transposed [n][k], fp16
__device__ float  g_score[NB * SEQ];         // raw scores
__device__ float  g_partial[NB * CTX_CHUNKS * DIM];

// ============================================================================
// Portable PTX helpers (base sm_80+ ISA only: cp.async + mma.sync)
// ============================================================================
static __device__ __forceinline__ uint32_t smem_u32(const void* p) {
    uint32_t a;
    asm("{ .reg .u64 t; cvta.to.shared.u64 t, %1; cvt.u32.u64 %0, t; }"
        : "=r"(a) : "l"(p));
    return a;
}

#define CP_ASYNC16(dst_u32, src_ptr) \
    asm volatile("cp.async.cg.shared.global [%0], [%1], 16;" \
                 :: "r"(dst_u32), "l"(src_ptr))
#define CP_COMMIT() asm volatile("cp.async.commit_group;" ::: "memory")
#define CP_WAIT(N)  asm volatile("cp.async.wait_group %0;" :: "n"(N) : "memory")

// mma.sync m16n8k16 f16 with fp32 accumulate: D = A*B + D
static __device__ __forceinline__ void mma_f16(
    float& d0, float& d1, float& d2, float& d3,
    uint32_t a0, uint32_t a1, uint32_t a2, uint32_t a3,
    uint32_t b0, uint32_t b1)
{
    asm volatile(
        "mma.sync.aligned.m16n8k16.row.col.f32.f16.f16.f32 "
        "{%0,%1,%2,%3}, {%4,%5,%6,%7}, {%8,%9}, {%0,%1,%2,%3};"
        : "+f"(d0), "+f"(d1), "+f"(d2), "+f"(d3)
        : "r"(a0), "r"(a1), "r"(a2), "r"(a3), "r"(b0), "r"(b1));
}

// fast tanh: 1 - 2/(e^{2x}+1); saturates correctly at +-inf; abs err ~1e-6
static __device__ __forceinline__ float fast_tanh(float x) {
    float e = __expf(2.0f * x);
    return 1.0f - __fdividef(2.0f, e + 1.0f);
}

// ============================================================================
// Dynamic SMEM layout for score kernel (bytes)
//   A tile (resident, fp16): 64 rows x 264 halfs (stride 264 -> word bank 4g+c)
//   B tile (2-stage, fp16):  256 rows x 40 halfs (stride 40 -> word bank 20g+c)
// ============================================================================
static constexpr int SME_Q   = 0;                      // 256 f32: q+b2
static constexpr int SME_V   = 1024;                   // 256 f32: v
static constexpr int SME_RED = 2048;                   // 4*64 f32
static constexpr int A_STRIDE_H = 264;                 // halfs per A row (528 B)
static constexpr int B_STRIDE_H = 40;                  // halfs per B row (80 B)
static constexpr int SME_AH  = 3072;
static constexpr int A_BYTES = BM * A_STRIDE_H * 2;    // 33792
static constexpr int SME_B0  = SME_AH + A_BYTES;       // 36864
static constexpr int B_STAGE = DIM * B_STRIDE_H * 2;   // 20480
static constexpr int SME_B1  = SME_B0 + B_STAGE;       // 57344
static constexpr int SMEM_TOTAL = SME_B1 + B_STAGE;    // 77824

// ============================================================================
// Kernel 1: q = dh @ w1 + b1   (fp32 exact, trivial cost)
// ============================================================================
__global__ void prep_q_kernel(const float* __restrict__ dh,
                              const float* __restrict__ w1,
                              const float* __restrict__ b1) {
    __shared__ float d[DIM];
    int b = blockIdx.x, a = threadIdx.x;
    d[a] = dh[b * DIM + a];
    __syncthreads();
    float acc = b1[a];
#pragma unroll 8
    for (int e = 0; e < DIM; ++e) acc = fmaf(d[e], w1[e * DIM + a], acc);
    g_q[b * DIM + a] = acc;
}

// ============================================================================
// Kernel 1b: w2t_h[n][k] = fp16(w2[k][n])  — tiled transpose, coalesced
// ============================================================================
__global__ void prep_w2t_kernel(const float* __restrict__ w2) {
    __shared__ float tile[32][33];
    int k0 = blockIdx.x * 32, n0 = blockIdx.y * 32;
    int tx = threadIdx.x, ty = threadIdx.y;
    tile[ty][tx] = w2[(k0 + ty) * DIM + n0 + tx];
    __syncthreads();
    g_w2t_h[(size_t)(n0 + ty) * DIM + k0 + tx] = __float2half_rn(tile[tx][ty]);
}

// ============================================================================
// Kernel 2: score[b][s] = v . tanh(q + b2 + enc@w2) + vbias
// fp16 mma.sync m16n8k16, BM=64 x BN=256 x K=256, fused tanh/dot epilogue.
// grid (NTILES_S, NB), 256 threads, 8 warps = 2(m) x 4(n), warp tile 32x64.
// A converted fp32->fp16 once and resident for all K; B 2-stage cp.async.
// ============================================================================
__global__ __launch_bounds__(256, 2)
void score_kernel(const float* __restrict__ enc,
                  const float* __restrict__ vker,
                  const float* __restrict__ vbias,
                  const float* __restrict__ b2) {
    extern __shared__ char smem[];
    const uint32_t sbase = smem_u32(smem);
    float* qs  = (float*)(smem + SME_Q);
    float* vs  = (float*)(smem + SME_V);
    float* red = (float*)(smem + SME_RED);

    const int tid = threadIdx.x;
    const int wid = tid >> 5, lid = tid & 31;
    const int wm = wid >> 2;          // 0..1  (m group: rows wm*32..+32)
    const int wn = wid & 3;           // 0..3  (n group: cols wn*64..+64)
    const int g  = lid >> 2;          // 0..7
    const int c  = lid & 3;           // 0..3
    const int b  = blockIdx.y;
    const int s0 = blockIdx.x * BM;

    // stage q+b2 and v
    qs[tid] = g_q[b * DIM + tid] + b2[tid];
    vs[tid] = vker[tid];
    const float vb0 = vbias[0];

    // ---- B stage loader (fp16, pre-transposed [n][k]) ---------------------
    auto load_B = [&](int stage, int kb) {
        const int k0 = kb * BK;
        uint32_t bbase = sbase + (stage ? SME_B1 : SME_B0);
        // 256 rows x 32 halfs = 256 x 64B = 1024 x 16B chunks, 4 per thread
#pragma unroll
        for (int i = 0; i < 4; ++i) {
            int idx = i * 256 + tid;
            int n = idx >> 2, j = idx & 3;
            uint32_t dst = bbase + (uint32_t)(n * (B_STRIDE_H * 2) + j * 16);
            CP_ASYNC16(dst, g_w2t_h + (size_t)n * DIM + k0 + j * 8);
        }
    };

    load_B(0, 0); CP_COMMIT();
    load_B(1, 1); CP_COMMIT();

    // ---- A: load fp32 tile, convert to fp16, keep resident for all K ------
    {
        const float* encA = enc + ((size_t)b * SEQ + s0) * DIM;
#pragma unroll
        for (int i = 0; i < 16; ++i) {
            int idx = i * 256 + tid;
            int r = idx >> 6, jq = idx & 63;           // jq: float4 index in row
            float4 v4 = *(const float4*)(encA + (size_t)r * DIM + jq * 4);
            __half2 h0 = __floats2half2_rn(v4.x, v4.y);
            __half2 h1 = __floats2half2_rn(v4.z, v4.w);
            uint2 u;
            u.x = *reinterpret_cast<uint32_t*>(&h0);
            u.y = *reinterpret_cast<uint32_t*>(&h1);
            *(uint2*)(smem + SME_AH + r * (A_STRIDE_H * 2) + jq * 8) = u;
        }
    }

    float acc[2][8][4];
#pragma unroll
    for (int mt = 0; mt < 2; ++mt)
#pragma unroll
        for (int nt = 0; nt < 8; ++nt)
#pragma unroll
            for (int j = 0; j < 4; ++j) acc[mt][nt][j] = 0.0f;

    const uint32_t* Ah = (const uint32_t*)(smem + SME_AH);   // word view
    // A fragment word base per mt: row*(A_STRIDE_H/2)
    const int ar0 = (wm * 32 + g) * (A_STRIDE_H / 2) + c;    // mt=0 rows
    const int ar1 = ar0 + 16 * (A_STRIDE_H / 2);             // mt=1 rows

    const int NKB = DIM / BK;   // 8
    for (int kb = 0; kb < NKB; ++kb) {
        if (kb < NKB - 2) { CP_WAIT(1); } else { CP_WAIT(0); }
        __syncthreads();

        const uint32_t* Bs = (const uint32_t*)(smem + ((kb & 1) ? SME_B1 : SME_B0));

#pragma unroll
        for (int ks = 0; ks < 2; ++ks) {
            const int khA = (kb * BK + ks * 16) >> 1;   // A word offset in row
            const int khB = ks * 8;                     // B word offset in row
            // A fragments (m16n8k16): a0={r,2c..},a1={r+8},a2={r,2c+8..},a3={r+8,+8}
            uint32_t af[2][4];
            {
                int i0 = ar0 + khA;
                af[0][0] = Ah[i0];
                af[0][1] = Ah[i0 + 8 * (A_STRIDE_H / 2)];
                af[0][2] = Ah[i0 + 4];
                af[0][3] = Ah[i0 + 8 * (A_STRIDE_H / 2) + 4];
                int i1 = ar1 + khA;
                af[1][0] = Ah[i1];
                af[1][1] = Ah[i1 + 8 * (A_STRIDE_H / 2)];
                af[1][2] = Ah[i1 + 4];
                af[1][3] = Ah[i1 + 8 * (A_STRIDE_H / 2) + 4];
            }
            // B fragments: b0={k=2c..2c+1, col}, b1={k=2c+8..,col}; Bt[n][k]
            uint32_t bf[8][2];
#pragma unroll
            for (int nt = 0; nt < 8; ++nt) {
                int nb = (wn * 64 + nt * 8 + g) * (B_STRIDE_H / 2) + khB + c;
                bf[nt][0] = Bs[nb];
                bf[nt][1] = Bs[nb + 4];
            }
#pragma unroll
            for (int mt = 0; mt < 2; ++mt)
#pragma unroll
                for (int nt = 0; nt < 8; ++nt)
                    mma_f16(acc[mt][nt][0], acc[mt][nt][1],
                            acc[mt][nt][2], acc[mt][nt][3],
                            af[mt][0], af[mt][1], af[mt][2], af[mt][3],
                            bf[nt][0], bf[nt][1]);
        }
        __syncthreads();
        if (kb + 2 < NKB) { load_B(kb & 1, kb + 2); CP_COMMIT(); }
    }

    // ---- epilogue: tanh(q + k) . v, reduce over N ------------------------
    // Thread holds rows {wm*32+mt*16+g, +8}, cols {wn*64+nt*8+2c, +1}
    // d0,d1 = row g cols 2c,2c+1 ; d2,d3 = row g+8
#pragma unroll
    for (int mt = 0; mt < 2; ++mt) {
#pragma unroll
        for (int h = 0; h < 2; ++h) {
            float p = 0.0f;
#pragma unroll
            for (int nt = 0; nt < 8; ++nt) {
#pragma unroll
                for (int j = 0; j < 2; ++j) {
                    int col = wn * 64 + nt * 8 + 2 * c + j;
                    float kv = acc[mt][nt][h * 2 + j];
                    p = fmaf(fast_tanh(qs[col] + kv), vs[col], p);
                }
            }
            // reduce over the 4 c-lanes (adjacent lanes)
            p += __shfl_xor_sync(0xFFFFFFFF, p, 1);
            p += __shfl_xor_sync(0xFFFFFFFF, p, 2);
            if (c == 0) {
                int row = wm * 32 + mt * 16 + g + h * 8;   // 0..63
                red[wn * 64 + row] = p;
            }
        }
    }
    __syncthreads();
    if (tid < BM) {
        float s = vb0 + red[tid] + red[64 + tid] + red[128 + tid] + red[192 + tid];
        g_score[b * SEQ + s0 + tid] = s;
    }
}

// ============================================================================
// Kernel 3: softmax over S per batch, writes attention weights to d_out
// 1024 threads, 4 elems each
// ============================================================================
__global__ __launch_bounds__(1024)
void softmax_kernel(float* __restrict__ out) {
    __shared__ float red[1024];
    const int b = blockIdx.x, tid = threadIdx.x;
    const float* s = g_score + b * SEQ;

    float v[4];
    float m = -1e30f;
#pragma unroll
    for (int j = 0; j < 4; ++j) {
        v[j] = s[tid + j * 1024];
        m = fmaxf(m, v[j]);
    }
    red[tid] = m; __syncthreads();
    for (int st = 512; st > 0; st >>= 1) {
        if (tid < st) red[tid] = fmaxf(red[tid], red[tid + st]);
        __syncthreads();
    }
    m = red[0]; __syncthreads();

    float sum = 0.0f;
#pragma unroll
    for (int j = 0; j < 4; ++j) { v[j] = expf(v[j] - m); sum += v[j]; }
    red[tid] = sum; __syncthreads();
    for (int st = 512; st > 0; st >>= 1) {
        if (tid < st) red[tid] += red[tid + st];
        __syncthreads();
    }
    const float inv = 1.0f / red[0];

    float* wout = out + NB * DIM + b * SEQ;   // weights after context region
#pragma unroll
    for (int j = 0; j < 4; ++j) wout[tid + j * 1024] = v[j] * inv;
}

// ============================================================================
// Kernel 4: partial context sums (deterministic split over S)
// grid (CTX_CHUNKS, NB) = (32, 32) -> 1024 CTAs for occupancy/MLP
// ============================================================================
__global__ void ctx_partial_kernel(const float* __restrict__ enc,
                                   const float* __restrict__ out) {
    __shared__ float ws[CTX_S];
    const int b = blockIdx.y, ch = blockIdx.x, tid = threadIdx.x;
    const float* wrow = out + NB * DIM + b * SEQ + ch * CTX_S;
    if (tid < CTX_S) ws[tid] = wrow[tid];
    __syncthreads();

    const float* e = enc + ((size_t)b * SEQ + ch * CTX_S) * DIM + tid;
    float a0 = 0.f, a1 = 0.f, a2 = 0.f, a3 = 0.f;
#pragma unroll 8
    for (int s = 0; s < CTX_S; s += 4) {
        a0 = fmaf(ws[s + 0], e[(size_t)(s + 0) * DIM], a0);
        a1 = fmaf(ws[s + 1], e[(size_t)(s + 1) * DIM], a1);
        a2 = fmaf(ws[s + 2], e[(size_t)(s + 2) * DIM], a2);
        a3 = fmaf(ws[s + 3], e[(size_t)(s + 3) * DIM], a3);
    }
    g_partial[(b * CTX_CHUNKS + ch) * DIM + tid] = (a0 + a1) + (a2 + a3);
}

// ============================================================================
// Kernel 5: final context reduction
// ============================================================================
__global__ void ctx_final_kernel(float* __restrict__ out) {
    const int b = blockIdx.x, a = threadIdx.x;
    float acc = 0.0f;
#pragma unroll
    for (int c = 0; c < CTX_CHUNKS; ++c)
        acc += g_partial[(b * CTX_CHUNKS + c) * DIM + a];
    out[b * DIM + a] = acc;
}

// ============================================================================
// kernel_launch
// ============================================================================
extern "C" void kernel_launch(void* const* d_in, const int* in_sizes, int n_in,
                              void* d_out, int out_size) {
    const float* dh  = (const float*)d_in[0];
    const float* enc = (const float*)d_in[1];
    const float* w1  = (const float*)d_in[2];
    const float* b1  = (const float*)d_in[3];
    const float* w2  = (const float*)d_in[4];
    const float* b2  = (const float*)d_in[5];
    const float* vk  = (const float*)d_in[6];
    const float* vb  = (const float*)d_in[7];
    float* out = (float*)d_out;

    cudaFuncSetAttribute(score_kernel,
                         cudaFuncAttributeMaxDynamicSharedMemorySize, SMEM_TOTAL);

    prep_q_kernel<<<NB, DIM>>>(dh, w1, b1);
    prep_w2t_kernel<<<dim3(8, 8), dim3(32, 32)>>>(w2);
    score_kernel<<<dim3(NTILES_S, NB), 256, SMEM_TOTAL>>>(enc, vk, vb, b2);
    softmax_kernel<<<NB, 1024>>>(out);
    ctx_partial_kernel<<<dim3(CTX_CHUNKS, NB), 256>>>(enc, out);
    ctx_final_kernel<<<NB, DIM>>>(out);
}

// round 7
// speedup vs baseline: 1.5348x; 1.0788x over previous
#include <cuda_runtime.h>
#include <cuda_fp16.h>
#include <cstdint>
#include <math.h>

// ============================================================================
// Problem constants
// ============================================================================
#define NB   32      // batch
#define SEQ  4096    // sequence length
#define DIM  256     // DEC_DIM == ENC_DIM == ATT_UNITS
#define BM   64      // s-rows per CTA
#define BK   32      // k per B pipeline stage
#define NTILES_S (SEQ / BM)             // 64
#define CTX_CHUNKS 32
#define CTX_S (SEQ / CTX_CHUNKS)        // 128

// ============================================================================
// Device scratch (no allocations allowed)
// ============================================================================
__device__ float  g_q[NB * DIM];             // q = dh@w1 + b1  (fp32 exact)
__device__ __half g_w2t_h[DIM * DIM];        // w2 transposed [n][k], fp16
__device__ float  g_score[NB * SEQ];         // raw scores
__device__ float  g_partial[NB * CTX_CHUNKS * DIM];

// ============================================================================
// Portable PTX helpers (base sm_75/80+ ISA: cp.async, ldmatrix, mma.sync)
// ============================================================================
static __device__ __forceinline__ uint32_t smem_u32(const void* p) {
    uint32_t a;
    asm("{ .reg .u64 t; cvta.to.shared.u64 t, %1; cvt.u32.u64 %0, t; }"
        : "=r"(a) : "l"(p));
    return a;
}

#define CP_ASYNC16(dst_u32, src_ptr) \
    asm volatile("cp.async.cg.shared.global [%0], [%1], 16;" \
                 :: "r"(dst_u32), "l"(src_ptr))
#define CP_COMMIT() asm volatile("cp.async.commit_group;" ::: "memory")
#define CP_WAIT(N)  asm volatile("cp.async.wait_group %0;" :: "n"(N) : "memory")

#define LDMX4(r0, r1, r2, r3, addr) \
    asm volatile("ldmatrix.sync.aligned.m8n8.x4.shared.b16 {%0,%1,%2,%3}, [%4];" \
                 : "=r"(r0), "=r"(r1), "=r"(r2), "=r"(r3) : "r"(addr))

// mma.sync m16n8k16 f16 with fp32 accumulate: D = A*B + D
static __device__ __forceinline__ void mma_f16(
    float& d0, float& d1, float& d2, float& d3,
    uint32_t a0, uint32_t a1, uint32_t a2, uint32_t a3,
    uint32_t b0, uint32_t b1)
{
    asm volatile(
        "mma.sync.aligned.m16n8k16.row.col.f32.f16.f16.f32 "
        "{%0,%1,%2,%3}, {%4,%5,%6,%7}, {%8,%9}, {%0,%1,%2,%3};"
        : "+f"(d0), "+f"(d1), "+f"(d2), "+f"(d3)
        : "r"(a0), "r"(a1), "r"(a2), "r"(a3), "r"(b0), "r"(b1));
}

// fast tanh: 1 - 2/(e^{2x}+1); saturates correctly at +-inf; abs err ~1e-6
static __device__ __forceinline__ float fast_tanh(float x) {
    float e = __expf(2.0f * x);
    return 1.0f - __fdividef(2.0f, e + 1.0f);
}

// ============================================================================
// Dynamic SMEM layout for score kernel (bytes)
//   A tile (resident, fp16): 64 rows x 264 halfs (132 words/row; ldmatrix quad
//     index (33r+o) mod 8 distinct over 8 rows -> conflict-free)
//   B tile (3-stage, fp16): 256 rows x 40 halfs (20 words/row; (5n+o) mod 8
//     distinct -> conflict-free)
// ============================================================================
static constexpr int SME_Q   = 0;                      // 256 f32: q+b2
static constexpr int SME_V   = 1024;                   // 256 f32: v
static constexpr int SME_RED = 2048;                   // 4*64 f32
static constexpr int A_STRIDE_H = 264;                 // halfs per A row (528 B)
static constexpr int B_STRIDE_H = 40;                  // halfs per B row (80 B)
static constexpr int SME_AH  = 3072;
static constexpr int A_BYTES = BM * A_STRIDE_H * 2;    // 33792
static constexpr int SME_B0  = SME_AH + A_BYTES;       // 36864
static constexpr int B_STAGE = DIM * B_STRIDE_H * 2;   // 20480
static constexpr int SMEM_TOTAL = SME_B0 + 3 * B_STAGE; // 98304

// ============================================================================
// Kernel 1: q = dh @ w1 + b1   (fp32 exact, trivial cost)
// ============================================================================
__global__ void prep_q_kernel(const float* __restrict__ dh,
                              const float* __restrict__ w1,
                              const float* __restrict__ b1) {
    __shared__ float d[DIM];
    int b = blockIdx.x, a = threadIdx.x;
    d[a] = dh[b * DIM + a];
    __syncthreads();
    float acc = b1[a];
#pragma unroll 8
    for (int e = 0; e < DIM; ++e) acc = fmaf(d[e], w1[e * DIM + a], acc);
    g_q[b * DIM + a] = acc;
}

// ============================================================================
// Kernel 1b: w2t_h[n][k] = fp16(w2[k][n])  — tiled transpose, coalesced
// ============================================================================
__global__ void prep_w2t_kernel(const float* __restrict__ w2) {
    __shared__ float tile[32][33];
    int k0 = blockIdx.x * 32, n0 = blockIdx.y * 32;
    int tx = threadIdx.x, ty = threadIdx.y;
    tile[ty][tx] = w2[(k0 + ty) * DIM + n0 + tx];
    __syncthreads();
    g_w2t_h[(size_t)(n0 + ty) * DIM + k0 + tx] = __float2half_rn(tile[tx][ty]);
}

// ============================================================================
// no-op kernel: shifts the hot score_kernel to ncu's captured launch slot
// ============================================================================
__global__ void nop_kernel() {}

// ============================================================================
// Kernel 2: score[b][s] = v . tanh(q + b2 + enc@w2) + vbias
// fp16 mma.sync m16n8k16, BM=64 x BN=256 x K=256, ldmatrix fragment loads,
// 3-stage cp.async B pipeline, fused tanh/dot epilogue.
// grid (NTILES_S, NB), 256 threads, 8 warps = 2(m) x 4(n), warp tile 32x64.
// ============================================================================
__global__ __launch_bounds__(256, 2)
void score_kernel(const float* __restrict__ enc,
                  const float* __restrict__ vker,
                  const float* __restrict__ vbias,
                  const float* __restrict__ b2) {
    extern __shared__ char smem[];
    const uint32_t sbase = smem_u32(smem);
    float* qs  = (float*)(smem + SME_Q);
    float* vs  = (float*)(smem + SME_V);
    float* red = (float*)(smem + SME_RED);

    const int tid = threadIdx.x;
    const int wid = tid >> 5, lid = tid & 31;
    const int wm = wid >> 2;          // 0..1  (m group: rows wm*32..+32)
    const int wn = wid & 3;           // 0..3  (n group: cols wn*64..+64)
    const int g  = lid >> 2;          // 0..7
    const int c  = lid & 3;           // 0..3
    const int b  = blockIdx.y;
    const int s0 = blockIdx.x * BM;

    // stage q+b2 and v
    qs[tid] = g_q[b * DIM + tid] + b2[tid];
    vs[tid] = vker[tid];
    const float vb0 = vbias[0];

    // ---- B stage loader (fp16, pre-transposed [n][k]) ---------------------
    auto load_B = [&](int stage, int kb) {
        const int k0 = kb * BK;
        uint32_t bbase = sbase + SME_B0 + stage * B_STAGE;
        // 256 rows x 32 halfs = 1024 x 16B chunks, 4 per thread
#pragma unroll
        for (int i = 0; i < 4; ++i) {
            int idx = i * 256 + tid;
            int n = idx >> 2, j = idx & 3;
            uint32_t dst = bbase + (uint32_t)(n * (B_STRIDE_H * 2) + j * 16);
            CP_ASYNC16(dst, g_w2t_h + (size_t)n * DIM + k0 + j * 8);
        }
    };

    load_B(0, 0); CP_COMMIT();
    load_B(1, 1); CP_COMMIT();

    // ---- A: load fp32 tile, convert to fp16, keep resident for all K ------
    {
        const float* encA = enc + ((size_t)b * SEQ + s0) * DIM;
#pragma unroll
        for (int i = 0; i < 16; ++i) {
            int idx = i * 256 + tid;
            int r = idx >> 6, jq = idx & 63;           // jq: float4 index in row
            float4 v4 = *(const float4*)(encA + (size_t)r * DIM + jq * 4);
            __half2 h0 = __floats2half2_rn(v4.x, v4.y);
            __half2 h1 = __floats2half2_rn(v4.z, v4.w);
            uint2 u;
            u.x = *reinterpret_cast<uint32_t*>(&h0);
            u.y = *reinterpret_cast<uint32_t*>(&h1);
            *(uint2*)(smem + SME_AH + r * (A_STRIDE_H * 2) + jq * 8) = u;
        }
    }
    load_B(2, 2); CP_COMMIT();

    float acc[2][8][4];
#pragma unroll
    for (int mt = 0; mt < 2; ++mt)
#pragma unroll
        for (int nt = 0; nt < 8; ++nt)
#pragma unroll
            for (int j = 0; j < 4; ++j) acc[mt][nt][j] = 0.0f;

    // ---- ldmatrix lane addresses ------------------------------------------
    // A x4: lanes 0-15 -> rows base+(lid&15) @k0 ; lanes 16-31 -> same rows @k0+8
    uint32_t a_addr[2];
#pragma unroll
    for (int mt = 0; mt < 2; ++mt) {
        int row = wm * 32 + mt * 16 + (lid & 15);
        int koff = (lid >> 4) * 8;
        a_addr[mt] = sbase + SME_AH + row * (A_STRIDE_H * 2) + koff * 2;
    }
    // B x4 (per nt pair): lanes 0-15 -> n rows nb+(lid&15) @k0 ; 16-31 @k0+8
    uint32_t b_off[4];
#pragma unroll
    for (int pr = 0; pr < 4; ++pr) {
        int n = wn * 64 + pr * 16 + (lid & 15);
        int koff = (lid >> 4) * 8;
        b_off[pr] = n * (B_STRIDE_H * 2) + koff * 2;
    }

    const int NKB = DIM / BK;   // 8
    for (int kb = 0; kb < NKB; ++kb) {
        if (kb <= NKB - 3)      { CP_WAIT(2); }
        else if (kb == NKB - 2) { CP_WAIT(1); }
        else                    { CP_WAIT(0); }
        __syncthreads();

        const uint32_t bstage = sbase + SME_B0 + (kb % 3) * B_STAGE;

#pragma unroll
        for (int ks = 0; ks < 2; ++ks) {
            const uint32_t kA = (uint32_t)(kb * BK + ks * 16) * 2;   // bytes
            uint32_t af[2][4];
            LDMX4(af[0][0], af[0][1], af[0][2], af[0][3], a_addr[0] + kA);
            LDMX4(af[1][0], af[1][1], af[1][2], af[1][3], a_addr[1] + kA);
            uint32_t bf[8][2];
#pragma unroll
            for (int pr = 0; pr < 4; ++pr) {
                uint32_t r0, r1, r2, r3;
                LDMX4(r0, r1, r2, r3, bstage + b_off[pr] + ks * 32);
                bf[2 * pr][0]     = r0;   // b0 of nt=2pr   (n rows nb..nb+7)
                bf[2 * pr + 1][0] = r1;   // b0 of nt=2pr+1 (n rows nb+8..15)
                bf[2 * pr][1]     = r2;   // b1 of nt=2pr
                bf[2 * pr + 1][1] = r3;   // b1 of nt=2pr+1
            }
#pragma unroll
            for (int mt = 0; mt < 2; ++mt)
#pragma unroll
                for (int nt = 0; nt < 8; ++nt)
                    mma_f16(acc[mt][nt][0], acc[mt][nt][1],
                            acc[mt][nt][2], acc[mt][nt][3],
                            af[mt][0], af[mt][1], af[mt][2], af[mt][3],
                            bf[nt][0], bf[nt][1]);
        }
        __syncthreads();
        if (kb + 3 < NKB) { load_B(kb % 3, kb + 3); CP_COMMIT(); }
    }

    // ---- epilogue: tanh(q + k) . v, reduce over N ------------------------
    // Thread holds rows {wm*32+mt*16+g, +8}, cols {wn*64+nt*8+2c, +1}
#pragma unroll
    for (int mt = 0; mt < 2; ++mt) {
#pragma unroll
        for (int h = 0; h < 2; ++h) {
            float p = 0.0f;
#pragma unroll
            for (int nt = 0; nt < 8; ++nt) {
#pragma unroll
                for (int j = 0; j < 2; ++j) {
                    int col = wn * 64 + nt * 8 + 2 * c + j;
                    float kv = acc[mt][nt][h * 2 + j];
                    p = fmaf(fast_tanh(qs[col] + kv), vs[col], p);
                }
            }
            p += __shfl_xor_sync(0xFFFFFFFF, p, 1);
            p += __shfl_xor_sync(0xFFFFFFFF, p, 2);
            if (c == 0) {
                int row = wm * 32 + mt * 16 + g + h * 8;   // 0..63
                red[wn * 64 + row] = p;
            }
        }
    }
    __syncthreads();
    if (tid < BM) {
        float s = vb0 + red[tid] + red[64 + tid] + red[128 + tid] + red[192 + tid];
        g_score[b * SEQ + s0 + tid] = s;
    }
}

// ============================================================================
// Kernel 3: softmax over S per batch, writes attention weights to d_out
// ============================================================================
__global__ __launch_bounds__(1024)
void softmax_kernel(float* __restrict__ out) {
    __shared__ float red[1024];
    const int b = blockIdx.x, tid = threadIdx.x;
    const float* s = g_score + b * SEQ;

    float v[4];
    float m = -1e30f;
#pragma unroll
    for (int j = 0; j < 4; ++j) {
        v[j] = s[tid + j * 1024];
        m = fmaxf(m, v[j]);
    }
    red[tid] = m; __syncthreads();
    for (int st = 512; st > 0; st >>= 1) {
        if (tid < st) red[tid] = fmaxf(red[tid], red[tid + st]);
        __syncthreads();
    }
    m = red[0]; __syncthreads();

    float sum = 0.0f;
#pragma unroll
    for (int j = 0; j < 4; ++j) { v[j] = expf(v[j] - m); sum += v[j]; }
    red[tid] = sum; __syncthreads();
    for (int st = 512; st > 0; st >>= 1) {
        if (tid < st) red[tid] += red[tid + st];
        __syncthreads();
    }
    const float inv = 1.0f / red[0];

    float* wout = out + NB * DIM + b * SEQ;   // weights after context region
#pragma unroll
    for (int j = 0; j < 4; ++j) wout[tid + j * 1024] = v[j] * inv;
}

// ============================================================================
// Kernel 4: partial context sums (deterministic split over S)
// ============================================================================
__global__ void ctx_partial_kernel(const float* __restrict__ enc,
                                   const float* __restrict__ out) {
    __shared__ float ws[CTX_S];
    const int b = blockIdx.y, ch = blockIdx.x, tid = threadIdx.x;
    const float* wrow = out + NB * DIM + b * SEQ + ch * CTX_S;
    if (tid < CTX_S) ws[tid] = wrow[tid];
    __syncthreads();

    const float* e = enc + ((size_t)b * SEQ + ch * CTX_S) * DIM + tid;
    float a0 = 0.f, a1 = 0.f, a2 = 0.f, a3 = 0.f;
#pragma unroll 8
    for (int s = 0; s < CTX_S; s += 4) {
        a0 = fmaf(ws[s + 0], e[(size_t)(s + 0) * DIM], a0);
        a1 = fmaf(ws[s + 1], e[(size_t)(s + 1) * DIM], a1);
        a2 = fmaf(ws[s + 2], e[(size_t)(s + 2) * DIM], a2);
        a3 = fmaf(ws[s + 3], e[(size_t)(s + 3) * DIM], a3);
    }
    g_partial[(b * CTX_CHUNKS + ch) * DIM + tid] = (a0 + a1) + (a2 + a3);
}

// ============================================================================
// Kernel 5: final context reduction
// ============================================================================
__global__ void ctx_final_kernel(float* __restrict__ out) {
    const int b = blockIdx.x, a = threadIdx.x;
    float acc = 0.0f;
#pragma unroll
    for (int c = 0; c < CTX_CHUNKS; ++c)
        acc += g_partial[(b * CTX_CHUNKS + c) * DIM + a];
    out[b * DIM + a] = acc;
}

// ============================================================================
// kernel_launch
// ============================================================================
extern "C" void kernel_launch(void* const* d_in, const int* in_sizes, int n_in,
                              void* d_out, int out_size) {
    const float* dh  = (const float*)d_in[0];
    const float* enc = (const float*)d_in[1];
    const float* w1  = (const float*)d_in[2];
    const float* b1  = (const float*)d_in[3];
    const float* w2  = (const float*)d_in[4];
    const float* b2  = (const float*)d_in[5];
    const float* vk  = (const float*)d_in[6];
    const float* vb  = (const float*)d_in[7];
    float* out = (float*)d_out;

    cudaFuncSetAttribute(score_kernel,
                         cudaFuncAttributeMaxDynamicSharedMemorySize, SMEM_TOTAL);

    prep_q_kernel<<<NB, DIM>>>(dh, w1, b1);
    prep_w2t_kernel<<<dim3(8, 8), dim3(32, 32)>>>(w2);
    nop_kernel<<<1, 32>>>();   // aligns score_kernel with ncu's captured slot
    score_kernel<<<dim3(NTILES_S, NB), 256, SMEM_TOTAL>>>(enc, vk, vb, b2);
    softmax_kernel<<<NB, 1024>>>(out);
    ctx_partial_kernel<<<dim3(CTX_CHUNKS, NB), 256>>>(enc, out);
    ctx_final_kernel<<<NB, DIM>>>(out);
}

// round 8
// speedup vs baseline: 1.5359x; 1.0007x over previous
#include <cuda_runtime.h>
#include <cuda_fp16.h>
#include <cstdint>
#include <math.h>

// ============================================================================
// Problem constants
// ============================================================================
#define NB   32      // batch
#define SEQ  4096    // sequence length
#define DIM  256     // DEC_DIM == ENC_DIM == ATT_UNITS
#define BM   64      // s-rows per CTA
#define BK   32      // k per B pipeline stage
#define NTILES_S (SEQ / BM)             // 64
#define CTX_CHUNKS 32
#define CTX_S (SEQ / CTX_CHUNKS)        // 128

// ============================================================================
// Device scratch (no allocations allowed)
// ============================================================================
__device__ float  g_q[NB * DIM];             // q = dh@w1 + b1  (fp32 exact)
__device__ __half g_w2t_h[DIM * DIM];        // w2 transposed [n][k], fp16
__device__ float  g_score[NB * SEQ];         // raw scores
__device__ float  g_partial[NB * CTX_CHUNKS * DIM];

// ============================================================================
// Portable PTX helpers (base sm_75/80+ ISA: cp.async, ldmatrix, mma.sync)
// ============================================================================
static __device__ __forceinline__ uint32_t smem_u32(const void* p) {
    uint32_t a;
    asm("{ .reg .u64 t; cvta.to.shared.u64 t, %1; cvt.u32.u64 %0, t; }"
        : "=r"(a) : "l"(p));
    return a;
}

#define CP_ASYNC16(dst_u32, src_ptr) \
    asm volatile("cp.async.cg.shared.global [%0], [%1], 16;" \
                 :: "r"(dst_u32), "l"(src_ptr))
#define CP_COMMIT() asm volatile("cp.async.commit_group;" ::: "memory")
#define CP_WAIT(N)  asm volatile("cp.async.wait_group %0;" :: "n"(N) : "memory")

#define LDMX4(r0, r1, r2, r3, addr) \
    asm volatile("ldmatrix.sync.aligned.m8n8.x4.shared.b16 {%0,%1,%2,%3}, [%4];" \
                 : "=r"(r0), "=r"(r1), "=r"(r2), "=r"(r3) : "r"(addr))

// mma.sync m16n8k16 f16 with fp32 accumulate: D = A*B + D
static __device__ __forceinline__ void mma_f16(
    float& d0, float& d1, float& d2, float& d3,
    uint32_t a0, uint32_t a1, uint32_t a2, uint32_t a3,
    uint32_t b0, uint32_t b1)
{
    asm volatile(
        "mma.sync.aligned.m16n8k16.row.col.f32.f16.f16.f32 "
        "{%0,%1,%2,%3}, {%4,%5,%6,%7}, {%8,%9}, {%0,%1,%2,%3};"
        : "+f"(d0), "+f"(d1), "+f"(d2), "+f"(d3)
        : "r"(a0), "r"(a1), "r"(a2), "r"(a3), "r"(b0), "r"(b1));
}

// fast tanh: 1 - 2/(e^{2x}+1); saturates correctly at +-inf; abs err ~1e-6
static __device__ __forceinline__ float fast_tanh(float x) {
    float e = __expf(2.0f * x);
    return 1.0f - __fdividef(2.0f, e + 1.0f);
}

// ============================================================================
// Dynamic SMEM layout for score kernel (bytes)
//   A tile (resident, fp16): 64 rows x 264 halfs (conflict-free for ldmatrix)
//   B tile (3-stage, fp16): 256 rows x 40 halfs (conflict-free for ldmatrix)
// ============================================================================
static constexpr int SME_Q   = 0;                      // 256 f32: q+b2
static constexpr int SME_V   = 1024;                   // 256 f32: v
static constexpr int SME_RED = 2048;                   // 4*64 f32
static constexpr int A_STRIDE_H = 264;                 // halfs per A row (528 B)
static constexpr int B_STRIDE_H = 40;                  // halfs per B row (80 B)
static constexpr int SME_AH  = 3072;
static constexpr int A_BYTES = BM * A_STRIDE_H * 2;    // 33792
static constexpr int SME_B0  = SME_AH + A_BYTES;       // 36864
static constexpr int B_STAGE = DIM * B_STRIDE_H * 2;   // 20480
static constexpr int SMEM_TOTAL = SME_B0 + 3 * B_STAGE; // 98304

// ============================================================================
// Kernel 1: q = dh @ w1 + b1   (fp32 exact, trivial cost)
// ============================================================================
__global__ void prep_q_kernel(const float* __restrict__ dh,
                              const float* __restrict__ w1,
                              const float* __restrict__ b1) {
    __shared__ float d[DIM];
    int b = blockIdx.x, a = threadIdx.x;
    d[a] = dh[b * DIM + a];
    __syncthreads();
    float acc = b1[a];
#pragma unroll 8
    for (int e = 0; e < DIM; ++e) acc = fmaf(d[e], w1[e * DIM + a], acc);
    g_q[b * DIM + a] = acc;
}

// ============================================================================
// Kernel 1b: w2t_h[n][k] = fp16(w2[k][n])  — tiled transpose, coalesced
// ============================================================================
__global__ void prep_w2t_kernel(const float* __restrict__ w2) {
    __shared__ float tile[32][33];
    int k0 = blockIdx.x * 32, n0 = blockIdx.y * 32;
    int tx = threadIdx.x, ty = threadIdx.y;
    tile[ty][tx] = w2[(k0 + ty) * DIM + n0 + tx];
    __syncthreads();
    g_w2t_h[(size_t)(n0 + ty) * DIM + k0 + tx] = __float2half_rn(tile[tx][ty]);
}

// ============================================================================
// no-op kernel: keeps score_kernel in ncu's captured launch slot
// ============================================================================
__global__ void nop_kernel() {}

// ============================================================================
// Kernel 2: score[b][s] = v . tanh(q + b2 + enc@w2) + vbias
// fp16 mma.sync m16n8k16, BM=64 x BN=256 x K=256, ldmatrix fragment loads,
// 3-stage cp.async B pipeline, FULLY UNROLLED mainloop (all addresses fold
// to immediates), fused tanh/dot epilogue.
// grid (NTILES_S, NB), 256 threads, 8 warps = 2(m) x 4(n), warp tile 32x64.
// ============================================================================
__global__ __launch_bounds__(256, 2)
void score_kernel(const float* __restrict__ enc,
                  const float* __restrict__ vker,
                  const float* __restrict__ vbias,
                  const float* __restrict__ b2) {
    extern __shared__ char smem[];
    const uint32_t sbase = smem_u32(smem);
    float* qs  = (float*)(smem + SME_Q);
    float* vs  = (float*)(smem + SME_V);
    float* red = (float*)(smem + SME_RED);

    const int tid = threadIdx.x;
    const int wid = tid >> 5, lid = tid & 31;
    const int wm = wid >> 2;          // 0..1  (m group: rows wm*32..+32)
    const int wn = wid & 3;           // 0..3  (n group: cols wn*64..+64)
    const int g  = lid >> 2;          // 0..7
    const int c  = lid & 3;           // 0..3
    const int b  = blockIdx.y;
    const int s0 = blockIdx.x * BM;

    // stage q+b2 and v
    qs[tid] = g_q[b * DIM + tid] + b2[tid];
    vs[tid] = vker[tid];
    const float vb0 = vbias[0];

    // ---- precomputed per-thread loader offsets (folded per unrolled kb) ---
    uint32_t ld_dst[4];          // smem offset within a B stage
    const __half* ld_src[4];     // gmem base (k0=0); advance by kb*BK
#pragma unroll
    for (int i = 0; i < 4; ++i) {
        int idx = i * 256 + tid;
        int n = idx >> 2, j = idx & 3;
        ld_dst[i] = (uint32_t)(n * (B_STRIDE_H * 2) + j * 16);
        ld_src[i] = g_w2t_h + (size_t)n * DIM + j * 8;
    }
    const uint32_t bS[3] = { sbase + SME_B0,
                             sbase + SME_B0 + B_STAGE,
                             sbase + SME_B0 + 2 * B_STAGE };

#define LOAD_B(stage, kb) do {                                     \
    _Pragma("unroll")                                              \
    for (int i = 0; i < 4; ++i)                                    \
        CP_ASYNC16(bS[stage] + ld_dst[i], ld_src[i] + (kb) * BK);  \
    CP_COMMIT();                                                   \
} while (0)

    LOAD_B(0, 0);
    LOAD_B(1, 1);

    // ---- A: load fp32 tile, convert to fp16, keep resident for all K ------
    {
        const float* encA = enc + ((size_t)b * SEQ + s0) * DIM;
#pragma unroll
        for (int i = 0; i < 16; ++i) {
            int idx = i * 256 + tid;
            int r = idx >> 6, jq = idx & 63;           // jq: float4 index in row
            float4 v4 = *(const float4*)(encA + (size_t)r * DIM + jq * 4);
            __half2 h0 = __floats2half2_rn(v4.x, v4.y);
            __half2 h1 = __floats2half2_rn(v4.z, v4.w);
            uint2 u;
            u.x = *reinterpret_cast<uint32_t*>(&h0);
            u.y = *reinterpret_cast<uint32_t*>(&h1);
            *(uint2*)(smem + SME_AH + r * (A_STRIDE_H * 2) + jq * 8) = u;
        }
    }
    LOAD_B(2, 2);

    float acc[2][8][4];
#pragma unroll
    for (int mt = 0; mt < 2; ++mt)
#pragma unroll
        for (int nt = 0; nt < 8; ++nt)
#pragma unroll
            for (int j = 0; j < 4; ++j) acc[mt][nt][j] = 0.0f;

    // ---- ldmatrix lane addresses (absolute; k offsets folded on unroll) ---
    uint32_t a_addr[2];
#pragma unroll
    for (int mt = 0; mt < 2; ++mt) {
        int row = wm * 32 + mt * 16 + (lid & 15);
        int koff = (lid >> 4) * 8;
        a_addr[mt] = sbase + SME_AH + row * (A_STRIDE_H * 2) + koff * 2;
    }
    uint32_t b_off[4];           // offset within a B stage
#pragma unroll
    for (int pr = 0; pr < 4; ++pr) {
        int n = wn * 64 + pr * 16 + (lid & 15);
        int koff = (lid >> 4) * 8;
        b_off[pr] = (uint32_t)(n * (B_STRIDE_H * 2) + koff * 2);
    }

    const int NKB = DIM / BK;   // 8
#pragma unroll
    for (int kb = 0; kb < NKB; ++kb) {
        if (kb <= NKB - 3)      { CP_WAIT(2); }
        else if (kb == NKB - 2) { CP_WAIT(1); }
        else                    { CP_WAIT(0); }
        __syncthreads();

        const uint32_t bstage = bS[kb % 3];

#pragma unroll
        for (int ks = 0; ks < 2; ++ks) {
            const uint32_t kA = (uint32_t)(kb * BK + ks * 16) * 2;   // bytes
            uint32_t af[2][4];
            LDMX4(af[0][0], af[0][1], af[0][2], af[0][3], a_addr[0] + kA);
            LDMX4(af[1][0], af[1][1], af[1][2], af[1][3], a_addr[1] + kA);
            uint32_t bf[8][2];
#pragma unroll
            for (int pr = 0; pr < 4; ++pr) {
                uint32_t r0, r1, r2, r3;
                LDMX4(r0, r1, r2, r3, bstage + b_off[pr] + ks * 32);
                bf[2 * pr][0]     = r0;
                bf[2 * pr + 1][0] = r1;
                bf[2 * pr][1]     = r2;
                bf[2 * pr + 1][1] = r3;
            }
#pragma unroll
            for (int mt = 0; mt < 2; ++mt)
#pragma unroll
                for (int nt = 0; nt < 8; ++nt)
                    mma_f16(acc[mt][nt][0], acc[mt][nt][1],
                            acc[mt][nt][2], acc[mt][nt][3],
                            af[mt][0], af[mt][1], af[mt][2], af[mt][3],
                            bf[nt][0], bf[nt][1]);
        }
        __syncthreads();
        if (kb + 3 < NKB) { LOAD_B((kb % 3), (kb + 3)); }
    }
#undef LOAD_B

    // ---- epilogue: tanh(q + k) . v, reduce over N ------------------------
#pragma unroll
    for (int mt = 0; mt < 2; ++mt) {
#pragma unroll
        for (int h = 0; h < 2; ++h) {
            float p = 0.0f;
#pragma unroll
            for (int nt = 0; nt < 8; ++nt) {
#pragma unroll
                for (int j = 0; j < 2; ++j) {
                    int col = wn * 64 + nt * 8 + 2 * c + j;
                    float kv = acc[mt][nt][h * 2 + j];
                    p = fmaf(fast_tanh(qs[col] + kv), vs[col], p);
                }
            }
            p += __shfl_xor_sync(0xFFFFFFFF, p, 1);
            p += __shfl_xor_sync(0xFFFFFFFF, p, 2);
            if (c == 0) {
                int row = wm * 32 + mt * 16 + g + h * 8;   // 0..63
                red[wn * 64 + row] = p;
            }
        }
    }
    __syncthreads();
    if (tid < BM) {
        float s = vb0 + red[tid] + red[64 + tid] + red[128 + tid] + red[192 + tid];
        g_score[b * SEQ + s0 + tid] = s;
    }
}

// ============================================================================
// Kernel 3: softmax over S per batch, writes attention weights to d_out
// ============================================================================
__global__ __launch_bounds__(1024)
void softmax_kernel(float* __restrict__ out) {
    __shared__ float red[1024];
    const int b = blockIdx.x, tid = threadIdx.x;
    const float* s = g_score + b * SEQ;

    float v[4];
    float m = -1e30f;
#pragma unroll
    for (int j = 0; j < 4; ++j) {
        v[j] = s[tid + j * 1024];
        m = fmaxf(m, v[j]);
    }
    red[tid] = m; __syncthreads();
    for (int st = 512; st > 0; st >>= 1) {
        if (tid < st) red[tid] = fmaxf(red[tid], red[tid + st]);
        __syncthreads();
    }
    m = red[0]; __syncthreads();

    float sum = 0.0f;
#pragma unroll
    for (int j = 0; j < 4; ++j) { v[j] = expf(v[j] - m); sum += v[j]; }
    red[tid] = sum; __syncthreads();
    for (int st = 512; st > 0; st >>= 1) {
        if (tid < st) red[tid] += red[tid + st];
        __syncthreads();
    }
    const float inv = 1.0f / red[0];

    float* wout = out + NB * DIM + b * SEQ;   // weights after context region
#pragma unroll
    for (int j = 0; j < 4; ++j) wout[tid + j * 1024] = v[j] * inv;
}

// ============================================================================
// Kernel 4: partial context sums (deterministic split over S)
// ============================================================================
__global__ void ctx_partial_kernel(const float* __restrict__ enc,
                                   const float* __restrict__ out) {
    __shared__ float ws[CTX_S];
    const int b = blockIdx.y, ch = blockIdx.x, tid = threadIdx.x;
    const float* wrow = out + NB * DIM + b * SEQ + ch * CTX_S;
    if (tid < CTX_S) ws[tid] = wrow[tid];
    __syncthreads();

    const float* e = enc + ((size_t)b * SEQ + ch * CTX_S) * DIM + tid;
    float a0 = 0.f, a1 = 0.f, a2 = 0.f, a3 = 0.f;
#pragma unroll 8
    for (int s = 0; s < CTX_S; s += 4) {
        a0 = fmaf(ws[s + 0], e[(size_t)(s + 0) * DIM], a0);
        a1 = fmaf(ws[s + 1], e[(size_t)(s + 1) * DIM], a1);
        a2 = fmaf(ws[s + 2], e[(size_t)(s + 2) * DIM], a2);
        a3 = fmaf(ws[s + 3], e[(size_t)(s + 3) * DIM], a3);
    }
    g_partial[(b * CTX_CHUNKS + ch) * DIM + tid] = (a0 + a1) + (a2 + a3);
}

// ============================================================================
// Kernel 5: final context reduction
// ============================================================================
__global__ void ctx_final_kernel(float* __restrict__ out) {
    const int b = blockIdx.x, a = threadIdx.x;
    float acc = 0.0f;
#pragma unroll
    for (int c = 0; c < CTX_CHUNKS; ++c)
        acc += g_partial[(b * CTX_CHUNKS + c) * DIM + a];
    out[b * DIM + a] = acc;
}

// ============================================================================
// kernel_launch
// ============================================================================
extern "C" void kernel_launch(void* const* d_in, const int* in_sizes, int n_in,
                              void* d_out, int out_size) {
    const float* dh  = (const float*)d_in[0];
    const float* enc = (const float*)d_in[1];
    const float* w1  = (const float*)d_in[2];
    const float* b1  = (const float*)d_in[3];
    const float* w2  = (const float*)d_in[4];
    const float* b2  = (const float*)d_in[5];
    const float* vk  = (const float*)d_in[6];
    const float* vb  = (const float*)d_in[7];
    float* out = (float*)d_out;

    cudaFuncSetAttribute(score_kernel,
                         cudaFuncAttributeMaxDynamicSharedMemorySize, SMEM_TOTAL);

    prep_q_kernel<<<NB, DIM>>>(dh, w1, b1);
    prep_w2t_kernel<<<dim3(8, 8), dim3(32, 32)>>>(w2);
    nop_kernel<<<1, 32>>>();   // aligns score_kernel with ncu's captured slot
    score_kernel<<<dim3(NTILES_S, NB), 256, SMEM_TOTAL>>>(enc, vk, vb, b2);
    softmax_kernel<<<NB, 1024>>>(out);
    ctx_partial_kernel<<<dim3(CTX_CHUNKS, NB), 256>>>(enc, out);
    ctx_final_kernel<<<NB, DIM>>>(out);
}